// round 1
// baseline (speedup 1.0000x reference)
#include <cuda_runtime.h>

// ============================================================================
// GroupBertAttention: pre-LN -> QKV proj -> MHA (softmax) -> out proj + residual
// B=2, S=2048, D=1024, H=16, hd=64, all fp32.
// Round 1: correct fp32 FFMA baseline. Tensor-core (tf32/tcgen05) in later rounds.
// ============================================================================

namespace {
constexpr int B = 2, S = 2048, D = 1024, H = 16, HD = 64;
constexpr int T = B * S;  // 4096 tokens
constexpr float LN_EPS = 1e-12f;
constexpr float SCALE = 0.125f;  // 1/sqrt(64)

// GEMM tiling
constexpr int BM = 128, BN = 64, BK = 16;
// attention tiling
constexpr int BQ = 128, BKV = 64;
}  // namespace

// Scratch (device globals; no allocation allowed in kernel_launch)
__device__ float g_xn[T * D];
__device__ float g_q[T * D];
__device__ float g_k[T * D];
__device__ float g_v[T * D];
__device__ float g_ctx[T * D];

// ----------------------------------------------------------------------------
// LayerNorm: one block per token, 256 threads x 4 elems
// ----------------------------------------------------------------------------
__global__ __launch_bounds__(256) void ln_kernel(const float* __restrict__ x,
                                                 const float* __restrict__ gamma,
                                                 const float* __restrict__ beta) {
    int t = blockIdx.x;
    int tid = threadIdx.x;
    const float4* row = reinterpret_cast<const float4*>(x + (size_t)t * D);
    float4 v = row[tid];
    float s = v.x + v.y + v.z + v.w;
    float ss = v.x * v.x + v.y * v.y + v.z * v.z + v.w * v.w;
#pragma unroll
    for (int o = 16; o > 0; o >>= 1) {
        s += __shfl_xor_sync(0xffffffffu, s, o);
        ss += __shfl_xor_sync(0xffffffffu, ss, o);
    }
    __shared__ float red_s[8], red_ss[8];
    int w = tid >> 5;
    if ((tid & 31) == 0) { red_s[w] = s; red_ss[w] = ss; }
    __syncthreads();
    s = 0.f; ss = 0.f;
#pragma unroll
    for (int i = 0; i < 8; i++) { s += red_s[i]; ss += red_ss[i]; }
    float mu = s * (1.f / (float)D);
    float var = ss * (1.f / (float)D) - mu * mu;
    float inv = rsqrtf(var + LN_EPS);
    float4 g = reinterpret_cast<const float4*>(gamma)[tid];
    float4 bb = reinterpret_cast<const float4*>(beta)[tid];
    float4 o;
    o.x = (v.x - mu) * inv * g.x + bb.x;
    o.y = (v.y - mu) * inv * g.y + bb.y;
    o.z = (v.z - mu) * inv * g.z + bb.z;
    o.w = (v.w - mu) * inv * g.w + bb.w;
    reinterpret_cast<float4*>(g_xn + (size_t)t * D)[tid] = o;
}

// ----------------------------------------------------------------------------
// GEMM core: C[M=4096, N=1024] = A[M,1024] @ W[N,1024]^T + bias (+ res)
// (torch Linear: both A and W are K-major)
// 128x64 block tile, BK=16, 256 threads, 8x4 per-thread microtile.
// ----------------------------------------------------------------------------
template <bool RES>
__device__ __forceinline__ void gemm_core(const float* __restrict__ A,
                                          const float* __restrict__ W,
                                          const float* __restrict__ bias,
                                          const float* __restrict__ res,
                                          float* __restrict__ C) {
    __shared__ float As[BK][BM];
    __shared__ float Bs[BK][BN];
    const int tid = threadIdx.x;
    const int m0 = blockIdx.y * BM;
    const int n0 = blockIdx.x * BN;
    const int tx = tid & 15;   // n: tx*4
    const int ty = tid >> 4;   // m: ty*8
    float acc[8][4];
#pragma unroll
    for (int i = 0; i < 8; i++)
#pragma unroll
        for (int j = 0; j < 4; j++) acc[i][j] = 0.f;

    const int ar = tid >> 1;         // 0..127 (A row in tile)
    const int ac = (tid & 1) * 2;    // float4 chunk base (0 or 2)
    const int br = tid >> 2;         // 0..63  (W row in tile)
    const int bc = tid & 3;          // float4 chunk

    for (int k0 = 0; k0 < D; k0 += BK) {
#pragma unroll
        for (int l = 0; l < 2; l++) {
            float4 a = *reinterpret_cast<const float4*>(
                A + (size_t)(m0 + ar) * D + k0 + (ac + l) * 4);
            As[(ac + l) * 4 + 0][ar] = a.x;
            As[(ac + l) * 4 + 1][ar] = a.y;
            As[(ac + l) * 4 + 2][ar] = a.z;
            As[(ac + l) * 4 + 3][ar] = a.w;
        }
        {
            float4 b4 = *reinterpret_cast<const float4*>(
                W + (size_t)(n0 + br) * D + k0 + bc * 4);
            Bs[bc * 4 + 0][br] = b4.x;
            Bs[bc * 4 + 1][br] = b4.y;
            Bs[bc * 4 + 2][br] = b4.z;
            Bs[bc * 4 + 3][br] = b4.w;
        }
        __syncthreads();
#pragma unroll
        for (int k = 0; k < BK; k++) {
            float4 b4 = *reinterpret_cast<const float4*>(&Bs[k][tx * 4]);
            float4 a0 = *reinterpret_cast<const float4*>(&As[k][ty * 8]);
            float4 a1 = *reinterpret_cast<const float4*>(&As[k][ty * 8 + 4]);
            float a[8] = {a0.x, a0.y, a0.z, a0.w, a1.x, a1.y, a1.z, a1.w};
#pragma unroll
            for (int i = 0; i < 8; i++) {
                acc[i][0] += a[i] * b4.x;
                acc[i][1] += a[i] * b4.y;
                acc[i][2] += a[i] * b4.z;
                acc[i][3] += a[i] * b4.w;
            }
        }
        __syncthreads();
    }
    float4 bi = *reinterpret_cast<const float4*>(bias + n0 + tx * 4);
#pragma unroll
    for (int i = 0; i < 8; i++) {
        size_t off = (size_t)(m0 + ty * 8 + i) * D + n0 + tx * 4;
        float4 o;
        o.x = acc[i][0] + bi.x;
        o.y = acc[i][1] + bi.y;
        o.z = acc[i][2] + bi.z;
        o.w = acc[i][3] + bi.w;
        if (RES) {
            float4 r = *reinterpret_cast<const float4*>(res + off);
            o.x += r.x; o.y += r.y; o.z += r.z; o.w += r.w;
        }
        *reinterpret_cast<float4*>(C + off) = o;
    }
}

__global__ __launch_bounds__(256) void gemm_qkv_kernel(
    const float* __restrict__ wq, const float* __restrict__ wk,
    const float* __restrict__ wv, const float* __restrict__ bq,
    const float* __restrict__ bk, const float* __restrict__ bv) {
    const float* Wm;
    const float* bias;
    float* out;
    if (blockIdx.z == 0)      { Wm = wq; bias = bq; out = g_q; }
    else if (blockIdx.z == 1) { Wm = wk; bias = bk; out = g_k; }
    else                      { Wm = wv; bias = bv; out = g_v; }
    gemm_core<false>(g_xn, Wm, bias, nullptr, out);
}

__global__ __launch_bounds__(256) void gemm_out_kernel(
    const float* __restrict__ wo, const float* __restrict__ bo,
    const float* __restrict__ residual, float* __restrict__ out) {
    gemm_core<true>(g_ctx, wo, bo, residual, out);
}

// ----------------------------------------------------------------------------
// Attention: one thread per query row (q[64], acc[64] in regs),
// K/V tiles of 64 keys in SMEM, broadcast float4 reads, online softmax with
// rarely-taken rescale branch. Scale folded into q.
// grid = (S/BQ=16, H=16, B=2), 128 threads.
// ----------------------------------------------------------------------------
__global__ __launch_bounds__(128) void attn_kernel(const float* __restrict__ mask) {
    const int qt = blockIdx.x;
    const int h = blockIdx.y;
    const int b = blockIdx.z;
    const int tid = threadIdx.x;
    const int q_s = qt * BQ + tid;  // query position within the sequence
    const size_t base = (size_t)b * S * D + (size_t)h * HD;

    __shared__ float Ks[BKV][HD];
    __shared__ float Vs[BKV][HD];
    __shared__ float Ms[BKV];

    float q[HD];
    {
        const float4* qrow = reinterpret_cast<const float4*>(g_q + base + (size_t)q_s * D);
#pragma unroll
        for (int i = 0; i < 16; i++) {
            float4 t4 = qrow[i];
            q[4 * i + 0] = t4.x * SCALE;
            q[4 * i + 1] = t4.y * SCALE;
            q[4 * i + 2] = t4.z * SCALE;
            q[4 * i + 3] = t4.w * SCALE;
        }
    }
    float acc[HD];
#pragma unroll
    for (int d = 0; d < HD; d++) acc[d] = 0.f;
    float m = -1e30f, l = 0.f;

    for (int kt = 0; kt < S; kt += BKV) {
        // load K/V tiles: 64 rows x 16 float4 = 1024 float4, 8 per thread
#pragma unroll
        for (int i = 0; i < 8; i++) {
            int e = tid + i * 128;
            int r = e >> 4;
            int c = e & 15;
            *reinterpret_cast<float4*>(&Ks[r][c * 4]) =
                *reinterpret_cast<const float4*>(g_k + base + (size_t)(kt + r) * D + c * 4);
            *reinterpret_cast<float4*>(&Vs[r][c * 4]) =
                *reinterpret_cast<const float4*>(g_v + base + (size_t)(kt + r) * D + c * 4);
        }
        if (tid < BKV) Ms[tid] = mask[(size_t)b * S + kt + tid];
        __syncthreads();

#pragma unroll 2
        for (int j = 0; j < BKV; j++) {
            float s0 = 0.f, s1 = 0.f, s2 = 0.f, s3 = 0.f;
#pragma unroll
            for (int d4 = 0; d4 < 16; d4++) {
                float4 kk = *reinterpret_cast<const float4*>(&Ks[j][d4 * 4]);
                s0 += q[4 * d4 + 0] * kk.x;
                s1 += q[4 * d4 + 1] * kk.y;
                s2 += q[4 * d4 + 2] * kk.z;
                s3 += q[4 * d4 + 3] * kk.w;
            }
            float sc = (s0 + s1) + (s2 + s3) + Ms[j];
            if (sc > m) {
                float corr = __expf(m - sc);
                m = sc;
                l *= corr;
#pragma unroll
                for (int d = 0; d < HD; d++) acc[d] *= corr;
            }
            float p = __expf(sc - m);
            l += p;
#pragma unroll
            for (int d4 = 0; d4 < 16; d4++) {
                float4 vv = *reinterpret_cast<const float4*>(&Vs[j][d4 * 4]);
                acc[4 * d4 + 0] += p * vv.x;
                acc[4 * d4 + 1] += p * vv.y;
                acc[4 * d4 + 2] += p * vv.z;
                acc[4 * d4 + 3] += p * vv.w;
            }
        }
        __syncthreads();
    }

    float inv = 1.f / l;
    float* orow = g_ctx + base + (size_t)q_s * D;
#pragma unroll
    for (int i = 0; i < 16; i++) {
        float4 o;
        o.x = acc[4 * i + 0] * inv;
        o.y = acc[4 * i + 1] * inv;
        o.z = acc[4 * i + 2] * inv;
        o.w = acc[4 * i + 3] * inv;
        *reinterpret_cast<float4*>(orow + 4 * i) = o;
    }
}

// ----------------------------------------------------------------------------
// Launch
// ----------------------------------------------------------------------------
extern "C" void kernel_launch(void* const* d_in, const int* in_sizes, int n_in,
                              void* d_out, int out_size) {
    (void)in_sizes; (void)n_in; (void)out_size;
    const float* hidden = (const float*)d_in[0];
    const float* mask   = (const float*)d_in[1];
    const float* gamma  = (const float*)d_in[2];
    const float* beta   = (const float*)d_in[3];
    const float* wq = (const float*)d_in[4];
    const float* bq = (const float*)d_in[5];
    const float* wk = (const float*)d_in[6];
    const float* bk = (const float*)d_in[7];
    const float* wv = (const float*)d_in[8];
    const float* bv = (const float*)d_in[9];
    const float* wo = (const float*)d_in[10];
    const float* bo = (const float*)d_in[11];
    float* out = (float*)d_out;

    ln_kernel<<<T, 256>>>(hidden, gamma, beta);

    dim3 gqkv(D / BN, T / BM, 3);  // (16, 32, 3)
    gemm_qkv_kernel<<<gqkv, 256>>>(wq, wk, wv, bq, bk, bv);

    dim3 gattn(S / BQ, H, B);  // (16, 16, 2)
    attn_kernel<<<gattn, 128>>>(mask);

    dim3 gout(D / BN, T / BM);  // (16, 32)
    gemm_out_kernel<<<gout, 256>>>(wo, bo, hidden, out);
}

// round 4
// speedup vs baseline: 1.3028x; 1.3028x over previous
#include <cuda_runtime.h>
#include <cstdint>

// ============================================================================
// GroupBertAttention: pre-LN -> QKV proj -> MHA (softmax) -> out proj + residual
// B=2, S=2048, D=1024, H=16, hd=64, fp32 in/out.
// Round 4 (3rd submission of the R2 kernel; two broker timeouts, never ran):
// linear GEMMs on tensor pipe via mma.sync.m16n8k8.tf32.
// Attention unchanged from the passing Round-1 version.
// ============================================================================

namespace {
constexpr int B = 2, S = 2048, D = 1024, H = 16, HD = 64;
constexpr int T = B * S;  // 4096 tokens
constexpr float LN_EPS = 1e-12f;
constexpr float SCALE = 0.125f;  // 1/sqrt(64)

// mma GEMM tiling
constexpr int BM = 128, BN = 128, BK = 16;
constexpr int LDK = 20;  // padded smem row stride (20g+tg mod 32 is a permutation)

// attention tiling
constexpr int BQ = 128, BKV = 64;
}  // namespace

// Scratch (device globals; no allocation allowed in kernel_launch)
__device__ float g_xn[T * D];
__device__ float g_q[T * D];
__device__ float g_k[T * D];
__device__ float g_v[T * D];
__device__ float g_ctx[T * D];

// ----------------------------------------------------------------------------
// LayerNorm: one block per token, 256 threads x 4 elems
// ----------------------------------------------------------------------------
__global__ __launch_bounds__(256) void ln_kernel(const float* __restrict__ x,
                                                 const float* __restrict__ gamma,
                                                 const float* __restrict__ beta) {
    int t = blockIdx.x;
    int tid = threadIdx.x;
    const float4* row = reinterpret_cast<const float4*>(x + (size_t)t * D);
    float4 v = row[tid];
    float s = v.x + v.y + v.z + v.w;
    float ss = v.x * v.x + v.y * v.y + v.z * v.z + v.w * v.w;
#pragma unroll
    for (int o = 16; o > 0; o >>= 1) {
        s += __shfl_xor_sync(0xffffffffu, s, o);
        ss += __shfl_xor_sync(0xffffffffu, ss, o);
    }
    __shared__ float red_s[8], red_ss[8];
    int w = tid >> 5;
    if ((tid & 31) == 0) { red_s[w] = s; red_ss[w] = ss; }
    __syncthreads();
    s = 0.f; ss = 0.f;
#pragma unroll
    for (int i = 0; i < 8; i++) { s += red_s[i]; ss += red_ss[i]; }
    float mu = s * (1.f / (float)D);
    float var = ss * (1.f / (float)D) - mu * mu;
    float inv = rsqrtf(var + LN_EPS);
    float4 g = reinterpret_cast<const float4*>(gamma)[tid];
    float4 bb = reinterpret_cast<const float4*>(beta)[tid];
    float4 o;
    o.x = (v.x - mu) * inv * g.x + bb.x;
    o.y = (v.y - mu) * inv * g.y + bb.y;
    o.z = (v.z - mu) * inv * g.z + bb.z;
    o.w = (v.w - mu) * inv * g.w + bb.w;
    reinterpret_cast<float4*>(g_xn + (size_t)t * D)[tid] = o;
}

// ----------------------------------------------------------------------------
// tf32 helpers
// ----------------------------------------------------------------------------
__device__ __forceinline__ float to_tf32(float x) {
    float r;
    asm("cvt.rna.tf32.f32 %0, %1;" : "=f"(r) : "f"(x));
    return r;
}

__device__ __forceinline__ void mma_tf32(float* d, const uint32_t* a, const uint32_t* b) {
    asm volatile(
        "mma.sync.aligned.m16n8k8.row.col.f32.tf32.tf32.f32 "
        "{%0,%1,%2,%3}, {%4,%5,%6,%7}, {%8,%9}, {%0,%1,%2,%3};"
        : "+f"(d[0]), "+f"(d[1]), "+f"(d[2]), "+f"(d[3])
        : "r"(a[0]), "r"(a[1]), "r"(a[2]), "r"(a[3]), "r"(b[0]), "r"(b[1]));
}

// ----------------------------------------------------------------------------
// GEMM core (tensor pipe): C[M=4096, N=1024] = A[M,K=1024] @ W[N,K]^T + bias (+res)
// Both A and W are K-major (torch Linear).
// Block 128x128, BK=16, 256 threads (8 warps: 4 m x 2 n), warp tile 32x64.
// mma m16n8k8 tf32; smem padded to LDK=20 for conflict-free fragment loads.
// ----------------------------------------------------------------------------
template <bool RES>
__device__ __forceinline__ void gemm_core_mma(const float* __restrict__ A,
                                              const float* __restrict__ W,
                                              const float* __restrict__ bias,
                                              const float* __restrict__ res,
                                              float* __restrict__ C) {
    __shared__ float As[BM * LDK];
    __shared__ float Bs[BN * LDK];
    const int tid = threadIdx.x;
    const int lane = tid & 31;
    const int wid = tid >> 5;
    const int wm = (wid & 3) * 32;   // warp row offset in tile
    const int wn = (wid >> 2) * 64;  // warp col offset in tile
    const int g = lane >> 2;         // groupID (0..7)
    const int tg = lane & 3;         // thread-in-group (0..3)
    const int m0 = blockIdx.y * BM;
    const int n0 = blockIdx.x * BN;

    float c[2][8][4];
#pragma unroll
    for (int mt = 0; mt < 2; mt++)
#pragma unroll
        for (int nt = 0; nt < 8; nt++)
#pragma unroll
            for (int i = 0; i < 4; i++) c[mt][nt][i] = 0.f;

    // global loaders: 256 threads fetch 128x16 tile as 2 float4 each
    const int lr = tid >> 2;        // 0..63
    const int lc = (tid & 3) * 4;   // k offset 0,4,8,12

    float4 pa0, pa1, pb0, pb1;
    pa0 = *reinterpret_cast<const float4*>(A + (size_t)(m0 + lr) * D + lc);
    pa1 = *reinterpret_cast<const float4*>(A + (size_t)(m0 + lr + 64) * D + lc);
    pb0 = *reinterpret_cast<const float4*>(W + (size_t)(n0 + lr) * D + lc);
    pb1 = *reinterpret_cast<const float4*>(W + (size_t)(n0 + lr + 64) * D + lc);

    for (int k0 = 0; k0 < D; k0 += BK) {
        // store prefetched tile to smem (tf32-rounded)
        float* as0 = As + lr * LDK + lc;
        as0[0] = to_tf32(pa0.x); as0[1] = to_tf32(pa0.y);
        as0[2] = to_tf32(pa0.z); as0[3] = to_tf32(pa0.w);
        float* as1 = As + (lr + 64) * LDK + lc;
        as1[0] = to_tf32(pa1.x); as1[1] = to_tf32(pa1.y);
        as1[2] = to_tf32(pa1.z); as1[3] = to_tf32(pa1.w);
        float* bs0 = Bs + lr * LDK + lc;
        bs0[0] = to_tf32(pb0.x); bs0[1] = to_tf32(pb0.y);
        bs0[2] = to_tf32(pb0.z); bs0[3] = to_tf32(pb0.w);
        float* bs1 = Bs + (lr + 64) * LDK + lc;
        bs1[0] = to_tf32(pb1.x); bs1[1] = to_tf32(pb1.y);
        bs1[2] = to_tf32(pb1.z); bs1[3] = to_tf32(pb1.w);
        __syncthreads();

        if (k0 + BK < D) {
            int kc = k0 + BK + lc;
            pa0 = *reinterpret_cast<const float4*>(A + (size_t)(m0 + lr) * D + kc);
            pa1 = *reinterpret_cast<const float4*>(A + (size_t)(m0 + lr + 64) * D + kc);
            pb0 = *reinterpret_cast<const float4*>(W + (size_t)(n0 + lr) * D + kc);
            pb1 = *reinterpret_cast<const float4*>(W + (size_t)(n0 + lr + 64) * D + kc);
        }

        // A fragments: [mt][kt][4]
        uint32_t af[2][2][4];
        const uint32_t* Asu = reinterpret_cast<const uint32_t*>(As);
#pragma unroll
        for (int mt = 0; mt < 2; mt++) {
            int r0 = wm + mt * 16 + g;
#pragma unroll
            for (int kt = 0; kt < 2; kt++) {
                int cbase = kt * 8 + tg;
                af[mt][kt][0] = Asu[r0 * LDK + cbase];
                af[mt][kt][1] = Asu[(r0 + 8) * LDK + cbase];
                af[mt][kt][2] = Asu[r0 * LDK + cbase + 4];
                af[mt][kt][3] = Asu[(r0 + 8) * LDK + cbase + 4];
            }
        }
        const uint32_t* Bsu = reinterpret_cast<const uint32_t*>(Bs);
#pragma unroll
        for (int nt = 0; nt < 8; nt++) {
            int nr = wn + nt * 8 + g;
            uint32_t bf[2][2];
#pragma unroll
            for (int kt = 0; kt < 2; kt++) {
                int cbase = kt * 8 + tg;
                bf[kt][0] = Bsu[nr * LDK + cbase];
                bf[kt][1] = Bsu[nr * LDK + cbase + 4];
            }
#pragma unroll
            for (int mt = 0; mt < 2; mt++) {
#pragma unroll
                for (int kt = 0; kt < 2; kt++) {
                    mma_tf32(c[mt][nt], af[mt][kt], bf[kt]);
                }
            }
        }
        __syncthreads();
    }

    // epilogue: bias (+ residual), float2 stores
#pragma unroll
    for (int nt = 0; nt < 8; nt++) {
        int col = n0 + wn + nt * 8 + 2 * tg;
        float2 bi = *reinterpret_cast<const float2*>(bias + col);
#pragma unroll
        for (int mt = 0; mt < 2; mt++) {
            int r0 = m0 + wm + mt * 16 + g;
#pragma unroll
            for (int half = 0; half < 2; half++) {
                int r = r0 + half * 8;
                size_t off = (size_t)r * D + col;
                float2 o;
                o.x = c[mt][nt][half * 2 + 0] + bi.x;
                o.y = c[mt][nt][half * 2 + 1] + bi.y;
                if (RES) {
                    float2 rr = *reinterpret_cast<const float2*>(res + off);
                    o.x += rr.x; o.y += rr.y;
                }
                *reinterpret_cast<float2*>(C + off) = o;
            }
        }
    }
}

__global__ __launch_bounds__(256) void gemm_qkv_kernel(
    const float* __restrict__ wq, const float* __restrict__ wk,
    const float* __restrict__ wv, const float* __restrict__ bq,
    const float* __restrict__ bk, const float* __restrict__ bv) {
    const float* Wm;
    const float* bias;
    float* out;
    if (blockIdx.z == 0)      { Wm = wq; bias = bq; out = g_q; }
    else if (blockIdx.z == 1) { Wm = wk; bias = bk; out = g_k; }
    else                      { Wm = wv; bias = bv; out = g_v; }
    gemm_core_mma<false>(g_xn, Wm, bias, nullptr, out);
}

__global__ __launch_bounds__(256) void gemm_out_kernel(
    const float* __restrict__ wo, const float* __restrict__ bo,
    const float* __restrict__ residual, float* __restrict__ out) {
    gemm_core_mma<true>(g_ctx, wo, bo, residual, out);
}

// ----------------------------------------------------------------------------
// Attention (unchanged passing version): one thread per query row,
// 64-key K/V SMEM tiles, online softmax, scale folded into q.
// grid = (S/BQ=16, H=16, B=2), 128 threads.
// ----------------------------------------------------------------------------
__global__ __launch_bounds__(128) void attn_kernel(const float* __restrict__ mask) {
    const int qt = blockIdx.x;
    const int h = blockIdx.y;
    const int b = blockIdx.z;
    const int tid = threadIdx.x;
    const int q_s = qt * BQ + tid;
    const size_t base = (size_t)b * S * D + (size_t)h * HD;

    __shared__ float Ks[BKV][HD];
    __shared__ float Vs[BKV][HD];
    __shared__ float Ms[BKV];

    float q[HD];
    {
        const float4* qrow = reinterpret_cast<const float4*>(g_q + base + (size_t)q_s * D);
#pragma unroll
        for (int i = 0; i < 16; i++) {
            float4 t4 = qrow[i];
            q[4 * i + 0] = t4.x * SCALE;
            q[4 * i + 1] = t4.y * SCALE;
            q[4 * i + 2] = t4.z * SCALE;
            q[4 * i + 3] = t4.w * SCALE;
        }
    }
    float acc[HD];
#pragma unroll
    for (int d = 0; d < HD; d++) acc[d] = 0.f;
    float m = -1e30f, l = 0.f;

    for (int kt = 0; kt < S; kt += BKV) {
#pragma unroll
        for (int i = 0; i < 8; i++) {
            int e = tid + i * 128;
            int r = e >> 4;
            int c = e & 15;
            *reinterpret_cast<float4*>(&Ks[r][c * 4]) =
                *reinterpret_cast<const float4*>(g_k + base + (size_t)(kt + r) * D + c * 4);
            *reinterpret_cast<float4*>(&Vs[r][c * 4]) =
                *reinterpret_cast<const float4*>(g_v + base + (size_t)(kt + r) * D + c * 4);
        }
        if (tid < BKV) Ms[tid] = mask[(size_t)b * S + kt + tid];
        __syncthreads();

#pragma unroll 2
        for (int j = 0; j < BKV; j++) {
            float s0 = 0.f, s1 = 0.f, s2 = 0.f, s3 = 0.f;
#pragma unroll
            for (int d4 = 0; d4 < 16; d4++) {
                float4 kk = *reinterpret_cast<const float4*>(&Ks[j][d4 * 4]);
                s0 += q[4 * d4 + 0] * kk.x;
                s1 += q[4 * d4 + 1] * kk.y;
                s2 += q[4 * d4 + 2] * kk.z;
                s3 += q[4 * d4 + 3] * kk.w;
            }
            float sc = (s0 + s1) + (s2 + s3) + Ms[j];
            if (sc > m) {
                float corr = __expf(m - sc);
                m = sc;
                l *= corr;
#pragma unroll
                for (int d = 0; d < HD; d++) acc[d] *= corr;
            }
            float p = __expf(sc - m);
            l += p;
#pragma unroll
            for (int d4 = 0; d4 < 16; d4++) {
                float4 vv = *reinterpret_cast<const float4*>(&Vs[j][d4 * 4]);
                acc[4 * d4 + 0] += p * vv.x;
                acc[4 * d4 + 1] += p * vv.y;
                acc[4 * d4 + 2] += p * vv.z;
                acc[4 * d4 + 3] += p * vv.w;
            }
        }
        __syncthreads();
    }

    float inv = 1.f / l;
    float* orow = g_ctx + base + (size_t)q_s * D;
#pragma unroll
    for (int i = 0; i < 16; i++) {
        float4 o;
        o.x = acc[4 * i + 0] * inv;
        o.y = acc[4 * i + 1] * inv;
        o.z = acc[4 * i + 2] * inv;
        o.w = acc[4 * i + 3] * inv;
        *reinterpret_cast<float4*>(orow + 4 * i) = o;
    }
}

// ----------------------------------------------------------------------------
// Launch
// ----------------------------------------------------------------------------
extern "C" void kernel_launch(void* const* d_in, const int* in_sizes, int n_in,
                              void* d_out, int out_size) {
    (void)in_sizes; (void)n_in; (void)out_size;
    const float* hidden = (const float*)d_in[0];
    const float* mask   = (const float*)d_in[1];
    const float* gamma  = (const float*)d_in[2];
    const float* beta   = (const float*)d_in[3];
    const float* wq = (const float*)d_in[4];
    const float* bq = (const float*)d_in[5];
    const float* wk = (const float*)d_in[6];
    const float* bk = (const float*)d_in[7];
    const float* wv = (const float*)d_in[8];
    const float* bv = (const float*)d_in[9];
    const float* wo = (const float*)d_in[10];
    const float* bo = (const float*)d_in[11];
    float* out = (float*)d_out;

    ln_kernel<<<T, 256>>>(hidden, gamma, beta);

    dim3 gqkv(D / BN, T / BM, 3);  // (8, 32, 3)
    gemm_qkv_kernel<<<gqkv, 256>>>(wq, wk, wv, bq, bk, bv);

    dim3 gattn(S / BQ, H, B);  // (16, 16, 2)
    attn_kernel<<<gattn, 128>>>(mask);

    dim3 gout(D / BN, T / BM);  // (8, 32)
    gemm_out_kernel<<<gout, 256>>>(wo, bo, hidden, out);
}

// round 6
// speedup vs baseline: 3.5021x; 2.6881x over previous
#include <cuda_runtime.h>
#include <cstdint>

// ============================================================================
// GroupBertAttention: pre-LN -> QKV proj -> MHA (softmax) -> out proj + residual
// B=2, S=2048, D=1024, H=16, hd=64, fp32 in/out.
// Round 6 (resubmit of R5; broker timeout, never ran): attention as tf32-MMA
// flash kernel (m16n8k8). Linear GEMMs/LN unchanged from R4 passing version.
// ============================================================================

namespace {
constexpr int B = 2, S = 2048, D = 1024, H = 16, HD = 64;
constexpr int T = B * S;  // 4096 tokens
constexpr float LN_EPS = 1e-12f;
constexpr float SCALE = 0.125f;  // 1/sqrt(64)

// mma GEMM tiling
constexpr int BM = 128, BN = 128, BK = 16;
constexpr int LDK = 20;  // padded smem row stride

// attention tiling
constexpr int ABQ = 128;   // queries per block
constexpr int ABK = 64;    // keys per tile
constexpr int LDA = 68;    // padded smem row stride for 64-wide tiles
}  // namespace

// Scratch (device globals; no allocation allowed in kernel_launch)
__device__ float g_xn[T * D];
__device__ float g_q[T * D];
__device__ float g_k[T * D];
__device__ float g_v[T * D];
__device__ float g_ctx[T * D];

// ----------------------------------------------------------------------------
// LayerNorm: one block per token, 256 threads x 4 elems
// ----------------------------------------------------------------------------
__global__ __launch_bounds__(256) void ln_kernel(const float* __restrict__ x,
                                                 const float* __restrict__ gamma,
                                                 const float* __restrict__ beta) {
    int t = blockIdx.x;
    int tid = threadIdx.x;
    const float4* row = reinterpret_cast<const float4*>(x + (size_t)t * D);
    float4 v = row[tid];
    float s = v.x + v.y + v.z + v.w;
    float ss = v.x * v.x + v.y * v.y + v.z * v.z + v.w * v.w;
#pragma unroll
    for (int o = 16; o > 0; o >>= 1) {
        s += __shfl_xor_sync(0xffffffffu, s, o);
        ss += __shfl_xor_sync(0xffffffffu, ss, o);
    }
    __shared__ float red_s[8], red_ss[8];
    int w = tid >> 5;
    if ((tid & 31) == 0) { red_s[w] = s; red_ss[w] = ss; }
    __syncthreads();
    s = 0.f; ss = 0.f;
#pragma unroll
    for (int i = 0; i < 8; i++) { s += red_s[i]; ss += red_ss[i]; }
    float mu = s * (1.f / (float)D);
    float var = ss * (1.f / (float)D) - mu * mu;
    float inv = rsqrtf(var + LN_EPS);
    float4 g = reinterpret_cast<const float4*>(gamma)[tid];
    float4 bb = reinterpret_cast<const float4*>(beta)[tid];
    float4 o;
    o.x = (v.x - mu) * inv * g.x + bb.x;
    o.y = (v.y - mu) * inv * g.y + bb.y;
    o.z = (v.z - mu) * inv * g.z + bb.z;
    o.w = (v.w - mu) * inv * g.w + bb.w;
    reinterpret_cast<float4*>(g_xn + (size_t)t * D)[tid] = o;
}

// ----------------------------------------------------------------------------
// tf32 helpers
// ----------------------------------------------------------------------------
__device__ __forceinline__ float to_tf32(float x) {
    float r;
    asm("cvt.rna.tf32.f32 %0, %1;" : "=f"(r) : "f"(x));
    return r;
}

__device__ __forceinline__ void mma_tf32(float* d, const uint32_t* a, const uint32_t* b) {
    asm volatile(
        "mma.sync.aligned.m16n8k8.row.col.f32.tf32.tf32.f32 "
        "{%0,%1,%2,%3}, {%4,%5,%6,%7}, {%8,%9}, {%0,%1,%2,%3};"
        : "+f"(d[0]), "+f"(d[1]), "+f"(d[2]), "+f"(d[3])
        : "r"(a[0]), "r"(a[1]), "r"(a[2]), "r"(a[3]), "r"(b[0]), "r"(b[1]));
}

// ----------------------------------------------------------------------------
// GEMM core (unchanged from R4 passing version)
// ----------------------------------------------------------------------------
template <bool RES>
__device__ __forceinline__ void gemm_core_mma(const float* __restrict__ A,
                                              const float* __restrict__ W,
                                              const float* __restrict__ bias,
                                              const float* __restrict__ res,
                                              float* __restrict__ C) {
    __shared__ float As[BM * LDK];
    __shared__ float Bs[BN * LDK];
    const int tid = threadIdx.x;
    const int lane = tid & 31;
    const int wid = tid >> 5;
    const int wm = (wid & 3) * 32;
    const int wn = (wid >> 2) * 64;
    const int g = lane >> 2;
    const int tg = lane & 3;
    const int m0 = blockIdx.y * BM;
    const int n0 = blockIdx.x * BN;

    float c[2][8][4];
#pragma unroll
    for (int mt = 0; mt < 2; mt++)
#pragma unroll
        for (int nt = 0; nt < 8; nt++)
#pragma unroll
            for (int i = 0; i < 4; i++) c[mt][nt][i] = 0.f;

    const int lr = tid >> 2;
    const int lc = (tid & 3) * 4;

    float4 pa0, pa1, pb0, pb1;
    pa0 = *reinterpret_cast<const float4*>(A + (size_t)(m0 + lr) * D + lc);
    pa1 = *reinterpret_cast<const float4*>(A + (size_t)(m0 + lr + 64) * D + lc);
    pb0 = *reinterpret_cast<const float4*>(W + (size_t)(n0 + lr) * D + lc);
    pb1 = *reinterpret_cast<const float4*>(W + (size_t)(n0 + lr + 64) * D + lc);

    for (int k0 = 0; k0 < D; k0 += BK) {
        float* as0 = As + lr * LDK + lc;
        as0[0] = to_tf32(pa0.x); as0[1] = to_tf32(pa0.y);
        as0[2] = to_tf32(pa0.z); as0[3] = to_tf32(pa0.w);
        float* as1 = As + (lr + 64) * LDK + lc;
        as1[0] = to_tf32(pa1.x); as1[1] = to_tf32(pa1.y);
        as1[2] = to_tf32(pa1.z); as1[3] = to_tf32(pa1.w);
        float* bs0 = Bs + lr * LDK + lc;
        bs0[0] = to_tf32(pb0.x); bs0[1] = to_tf32(pb0.y);
        bs0[2] = to_tf32(pb0.z); bs0[3] = to_tf32(pb0.w);
        float* bs1 = Bs + (lr + 64) * LDK + lc;
        bs1[0] = to_tf32(pb1.x); bs1[1] = to_tf32(pb1.y);
        bs1[2] = to_tf32(pb1.z); bs1[3] = to_tf32(pb1.w);
        __syncthreads();

        if (k0 + BK < D) {
            int kc = k0 + BK + lc;
            pa0 = *reinterpret_cast<const float4*>(A + (size_t)(m0 + lr) * D + kc);
            pa1 = *reinterpret_cast<const float4*>(A + (size_t)(m0 + lr + 64) * D + kc);
            pb0 = *reinterpret_cast<const float4*>(W + (size_t)(n0 + lr) * D + kc);
            pb1 = *reinterpret_cast<const float4*>(W + (size_t)(n0 + lr + 64) * D + kc);
        }

        uint32_t af[2][2][4];
        const uint32_t* Asu = reinterpret_cast<const uint32_t*>(As);
#pragma unroll
        for (int mt = 0; mt < 2; mt++) {
            int r0 = wm + mt * 16 + g;
#pragma unroll
            for (int kt = 0; kt < 2; kt++) {
                int cbase = kt * 8 + tg;
                af[mt][kt][0] = Asu[r0 * LDK + cbase];
                af[mt][kt][1] = Asu[(r0 + 8) * LDK + cbase];
                af[mt][kt][2] = Asu[r0 * LDK + cbase + 4];
                af[mt][kt][3] = Asu[(r0 + 8) * LDK + cbase + 4];
            }
        }
        const uint32_t* Bsu = reinterpret_cast<const uint32_t*>(Bs);
#pragma unroll
        for (int nt = 0; nt < 8; nt++) {
            int nr = wn + nt * 8 + g;
            uint32_t bf[2][2];
#pragma unroll
            for (int kt = 0; kt < 2; kt++) {
                int cbase = kt * 8 + tg;
                bf[kt][0] = Bsu[nr * LDK + cbase];
                bf[kt][1] = Bsu[nr * LDK + cbase + 4];
            }
#pragma unroll
            for (int mt = 0; mt < 2; mt++) {
#pragma unroll
                for (int kt = 0; kt < 2; kt++) {
                    mma_tf32(c[mt][nt], af[mt][kt], bf[kt]);
                }
            }
        }
        __syncthreads();
    }

#pragma unroll
    for (int nt = 0; nt < 8; nt++) {
        int col = n0 + wn + nt * 8 + 2 * tg;
        float2 bi = *reinterpret_cast<const float2*>(bias + col);
#pragma unroll
        for (int mt = 0; mt < 2; mt++) {
            int r0 = m0 + wm + mt * 16 + g;
#pragma unroll
            for (int half = 0; half < 2; half++) {
                int r = r0 + half * 8;
                size_t off = (size_t)r * D + col;
                float2 o;
                o.x = c[mt][nt][half * 2 + 0] + bi.x;
                o.y = c[mt][nt][half * 2 + 1] + bi.y;
                if (RES) {
                    float2 rr = *reinterpret_cast<const float2*>(res + off);
                    o.x += rr.x; o.y += rr.y;
                }
                *reinterpret_cast<float2*>(C + off) = o;
            }
        }
    }
}

__global__ __launch_bounds__(256) void gemm_qkv_kernel(
    const float* __restrict__ wq, const float* __restrict__ wk,
    const float* __restrict__ wv, const float* __restrict__ bq,
    const float* __restrict__ bk, const float* __restrict__ bv) {
    const float* Wm;
    const float* bias;
    float* out;
    if (blockIdx.z == 0)      { Wm = wq; bias = bq; out = g_q; }
    else if (blockIdx.z == 1) { Wm = wk; bias = bk; out = g_k; }
    else                      { Wm = wv; bias = bv; out = g_v; }
    gemm_core_mma<false>(g_xn, Wm, bias, nullptr, out);
}

__global__ __launch_bounds__(256) void gemm_out_kernel(
    const float* __restrict__ wo, const float* __restrict__ bo,
    const float* __restrict__ residual, float* __restrict__ out) {
    gemm_core_mma<true>(g_ctx, wo, bo, residual, out);
}

// ----------------------------------------------------------------------------
// Flash attention, tf32 mma m16n8k8.
// Block: 128 queries x one (b,h). 8 warps x 16 q-rows each. Key tiles of 64.
// S = Q K^T  : A=Q[16,64] row-major frags, B=Ks[key][d] (col-major k8n8).
// O += P V   : A=P frags built from S C-frags via quad shuffles,
//              B=Vt[d][key] (V transposed in smem).
// Online softmax on fragments; per-thread partial l, reduced at end.
// grid = (S/128=16, H=16, B=2), 256 threads.
// ----------------------------------------------------------------------------
__global__ __launch_bounds__(256, 1) void attn_mma_kernel(const float* __restrict__ mask) {
    __shared__ float buf[ABQ * LDA];   // Q stage, then K(0..64*LDA) / Vt(64*LDA..)
    __shared__ float Ms_[ABK];
    float* Ks = buf;
    float* Vt = buf + 64 * LDA;

    const int qt = blockIdx.x;
    const int h = blockIdx.y;
    const int b = blockIdx.z;
    const int tid = threadIdx.x;
    const int lane = tid & 31;
    const int wid = tid >> 5;
    const int g = lane >> 2;
    const int tg = lane & 3;
    const int wm = wid * 16;  // warp's q-row offset in block
    const size_t base = (size_t)b * S * D + (size_t)h * HD;

    // ---- stage Q (scaled, tf32) into buf, extract per-warp fragments ----
    {
        int r = tid >> 1;
        const float* qrow = g_q + base + (size_t)(qt * ABQ + r) * D;
#pragma unroll
        for (int j = 0; j < 8; j++) {
            int c4 = (tid & 1) * 8 + j;
            float4 v = *reinterpret_cast<const float4*>(qrow + c4 * 4);
            float* dst = buf + r * LDA + c4 * 4;
            dst[0] = to_tf32(v.x * SCALE);
            dst[1] = to_tf32(v.y * SCALE);
            dst[2] = to_tf32(v.z * SCALE);
            dst[3] = to_tf32(v.w * SCALE);
        }
    }
    __syncthreads();

    uint32_t aq[8][4];
    {
        const uint32_t* Qu = reinterpret_cast<const uint32_t*>(buf);
#pragma unroll
        for (int dk = 0; dk < 8; dk++) {
            int cb = dk * 8 + tg;
            aq[dk][0] = Qu[(wm + g) * LDA + cb];
            aq[dk][1] = Qu[(wm + g + 8) * LDA + cb];
            aq[dk][2] = Qu[(wm + g) * LDA + cb + 4];
            aq[dk][3] = Qu[(wm + g + 8) * LDA + cb + 4];
        }
    }
    __syncthreads();  // done with Q stage; buf becomes K/Vt

    float co[8][4];
#pragma unroll
    for (int nt = 0; nt < 8; nt++)
#pragma unroll
        for (int i = 0; i < 4; i++) co[nt][i] = 0.f;
    float m0 = -1e30f, m1 = -1e30f, l0 = 0.f, l1 = 0.f;

    const int key_of_t = tid >> 2;       // 0..63
    const int c4base = tid & 3;          // chunk base

    for (int kt0 = 0; kt0 < S; kt0 += ABK) {
        // ---- load K tile [key][d] and V tile transposed [d][key], tf32 ----
        const float* krow = g_k + base + (size_t)(kt0 + key_of_t) * D;
        const float* vrow = g_v + base + (size_t)(kt0 + key_of_t) * D;
#pragma unroll
        for (int j = 0; j < 4; j++) {
            int c4 = c4base + j * 4;
            float4 kv = *reinterpret_cast<const float4*>(krow + c4 * 4);
            float* kd = Ks + key_of_t * LDA + c4 * 4;
            kd[0] = to_tf32(kv.x); kd[1] = to_tf32(kv.y);
            kd[2] = to_tf32(kv.z); kd[3] = to_tf32(kv.w);
            float4 vv = *reinterpret_cast<const float4*>(vrow + c4 * 4);
            Vt[(c4 * 4 + 0) * LDA + key_of_t] = to_tf32(vv.x);
            Vt[(c4 * 4 + 1) * LDA + key_of_t] = to_tf32(vv.y);
            Vt[(c4 * 4 + 2) * LDA + key_of_t] = to_tf32(vv.z);
            Vt[(c4 * 4 + 3) * LDA + key_of_t] = to_tf32(vv.w);
        }
        if (tid < ABK) Ms_[tid] = mask[(size_t)b * S + kt0 + tid];
        __syncthreads();

        // ---- S = Q K^T ----
        float cs[8][4];
#pragma unroll
        for (int nt = 0; nt < 8; nt++)
#pragma unroll
            for (int i = 0; i < 4; i++) cs[nt][i] = 0.f;

        const uint32_t* Ksu = reinterpret_cast<const uint32_t*>(Ks);
#pragma unroll
        for (int dk = 0; dk < 8; dk++) {
#pragma unroll
            for (int nt = 0; nt < 8; nt++) {
                uint32_t bf[2];
                bf[0] = Ksu[(nt * 8 + g) * LDA + dk * 8 + tg];
                bf[1] = Ksu[(nt * 8 + g) * LDA + dk * 8 + tg + 4];
                mma_tf32(cs[nt], aq[dk], bf);
            }
        }

        // ---- mask + online softmax on fragments ----
        float mx0 = -1e30f, mx1 = -1e30f;
#pragma unroll
        for (int nt = 0; nt < 8; nt++) {
            float mk0 = Ms_[nt * 8 + 2 * tg];
            float mk1 = Ms_[nt * 8 + 2 * tg + 1];
            cs[nt][0] += mk0; cs[nt][1] += mk1;
            cs[nt][2] += mk0; cs[nt][3] += mk1;
            mx0 = fmaxf(mx0, fmaxf(cs[nt][0], cs[nt][1]));
            mx1 = fmaxf(mx1, fmaxf(cs[nt][2], cs[nt][3]));
        }
        mx0 = fmaxf(mx0, __shfl_xor_sync(0xffffffffu, mx0, 1));
        mx0 = fmaxf(mx0, __shfl_xor_sync(0xffffffffu, mx0, 2));
        mx1 = fmaxf(mx1, __shfl_xor_sync(0xffffffffu, mx1, 1));
        mx1 = fmaxf(mx1, __shfl_xor_sync(0xffffffffu, mx1, 2));

        float mn0 = fmaxf(m0, mx0);
        float mn1 = fmaxf(m1, mx1);
        float cr0 = __expf(m0 - mn0);
        float cr1 = __expf(m1 - mn1);
        m0 = mn0; m1 = mn1;
        l0 *= cr0; l1 *= cr1;

        uint32_t pu[8][4];
#pragma unroll
        for (int nt = 0; nt < 8; nt++) {
            float p0 = __expf(cs[nt][0] - m0);
            float p1 = __expf(cs[nt][1] - m0);
            float p2 = __expf(cs[nt][2] - m1);
            float p3 = __expf(cs[nt][3] - m1);
            l0 += p0 + p1;
            l1 += p2 + p3;
            pu[nt][0] = __float_as_uint(to_tf32(p0));
            pu[nt][1] = __float_as_uint(to_tf32(p1));
            pu[nt][2] = __float_as_uint(to_tf32(p2));
            pu[nt][3] = __float_as_uint(to_tf32(p3));
            co[nt][0] *= cr0; co[nt][1] *= cr0;
            co[nt][2] *= cr1; co[nt][3] *= cr1;
        }

        // ---- O += P V : rearrange P C-frags -> A-frags (quad shuffles), mma ----
        const uint32_t* Vtu = reinterpret_cast<const uint32_t*>(Vt);
        const int srcA = (lane & ~3) | (tg >> 1);
        const int srcB = srcA + 2;
#pragma unroll
        for (int kk = 0; kk < 8; kk++) {
            uint32_t v00 = __shfl_sync(0xffffffffu, pu[kk][0], srcA);
            uint32_t v01 = __shfl_sync(0xffffffffu, pu[kk][1], srcA);
            uint32_t v10 = __shfl_sync(0xffffffffu, pu[kk][2], srcA);
            uint32_t v11 = __shfl_sync(0xffffffffu, pu[kk][3], srcA);
            uint32_t w00 = __shfl_sync(0xffffffffu, pu[kk][0], srcB);
            uint32_t w01 = __shfl_sync(0xffffffffu, pu[kk][1], srcB);
            uint32_t w10 = __shfl_sync(0xffffffffu, pu[kk][2], srcB);
            uint32_t w11 = __shfl_sync(0xffffffffu, pu[kk][3], srcB);
            uint32_t ap[4];
            ap[0] = (tg & 1) ? v01 : v00;  // (row g,   key kk*8+tg)
            ap[1] = (tg & 1) ? v11 : v10;  // (row g+8, key kk*8+tg)
            ap[2] = (tg & 1) ? w01 : w00;  // (row g,   key kk*8+tg+4)
            ap[3] = (tg & 1) ? w11 : w10;  // (row g+8, key kk*8+tg+4)
#pragma unroll
            for (int nt = 0; nt < 8; nt++) {
                uint32_t bf[2];
                bf[0] = Vtu[(nt * 8 + g) * LDA + kk * 8 + tg];
                bf[1] = Vtu[(nt * 8 + g) * LDA + kk * 8 + tg + 4];
                mma_tf32(co[nt], ap, bf);
            }
        }
        __syncthreads();
    }

    // ---- finalize: reduce l across quad, normalize, store ----
    l0 += __shfl_xor_sync(0xffffffffu, l0, 1);
    l0 += __shfl_xor_sync(0xffffffffu, l0, 2);
    l1 += __shfl_xor_sync(0xffffffffu, l1, 1);
    l1 += __shfl_xor_sync(0xffffffffu, l1, 2);
    float inv0 = 1.f / l0;
    float inv1 = 1.f / l1;

    const int qr0 = qt * ABQ + wm + g;
#pragma unroll
    for (int nt = 0; nt < 8; nt++) {
        int col = nt * 8 + 2 * tg;
        float2 o0, o1;
        o0.x = co[nt][0] * inv0; o0.y = co[nt][1] * inv0;
        o1.x = co[nt][2] * inv1; o1.y = co[nt][3] * inv1;
        *reinterpret_cast<float2*>(g_ctx + base + (size_t)qr0 * D + col) = o0;
        *reinterpret_cast<float2*>(g_ctx + base + (size_t)(qr0 + 8) * D + col) = o1;
    }
}

// ----------------------------------------------------------------------------
// Launch
// ----------------------------------------------------------------------------
extern "C" void kernel_launch(void* const* d_in, const int* in_sizes, int n_in,
                              void* d_out, int out_size) {
    (void)in_sizes; (void)n_in; (void)out_size;
    const float* hidden = (const float*)d_in[0];
    const float* mask   = (const float*)d_in[1];
    const float* gamma  = (const float*)d_in[2];
    const float* beta   = (const float*)d_in[3];
    const float* wq = (const float*)d_in[4];
    const float* bq = (const float*)d_in[5];
    const float* wk = (const float*)d_in[6];
    const float* bk = (const float*)d_in[7];
    const float* wv = (const float*)d_in[8];
    const float* bv = (const float*)d_in[9];
    const float* wo = (const float*)d_in[10];
    const float* bo = (const float*)d_in[11];
    float* out = (float*)d_out;

    ln_kernel<<<T, 256>>>(hidden, gamma, beta);

    dim3 gqkv(D / BN, T / BM, 3);  // (8, 32, 3)
    gemm_qkv_kernel<<<gqkv, 256>>>(wq, wk, wv, bq, bk, bv);

    dim3 gattn(S / ABQ, H, B);  // (16, 16, 2)
    attn_mma_kernel<<<gattn, 256>>>(mask);

    dim3 gout(D / BN, T / BM);  // (8, 32)
    gemm_out_kernel<<<gout, 256>>>(wo, bo, hidden, out);
}

// round 11
// speedup vs baseline: 3.7026x; 1.0572x over previous
#include <cuda_runtime.h>
#include <cstdint>

// ============================================================================
// GroupBertAttention: pre-LN -> QKV proj -> MHA (softmax) -> out proj + residual
// B=2, S=2048, D=1024, H=16, hd=64, fp32 in/out.
// Round 11 (5th submission of R7 kernel; broker timeouts, never ran):
// linear GEMMs with cp.async 2-stage double-buffered mainloop (tf32 via mma
// truncation). Attention unchanged from the R6 passing MMA-flash kernel.
// ============================================================================

namespace {
constexpr int B = 2, S = 2048, D = 1024, H = 16, HD = 64;
constexpr int T = B * S;  // 4096 tokens
constexpr float LN_EPS = 1e-12f;
constexpr float SCALE = 0.125f;  // 1/sqrt(64)

// mma GEMM tiling
constexpr int BM = 128, BN = 128, BK = 16;
constexpr int LDK = 20;  // padded smem row stride
constexpr int NK = D / BK;  // 64

// attention tiling
constexpr int ABQ = 128;   // queries per block
constexpr int ABK = 64;    // keys per tile
constexpr int LDA = 68;    // padded smem row stride for 64-wide tiles
}  // namespace

// Scratch (device globals; no allocation allowed in kernel_launch)
__device__ float g_xn[T * D];
__device__ float g_q[T * D];
__device__ float g_k[T * D];
__device__ float g_v[T * D];
__device__ float g_ctx[T * D];

// ----------------------------------------------------------------------------
// LayerNorm: one block per token, 256 threads x 4 elems
// ----------------------------------------------------------------------------
__global__ __launch_bounds__(256) void ln_kernel(const float* __restrict__ x,
                                                 const float* __restrict__ gamma,
                                                 const float* __restrict__ beta) {
    int t = blockIdx.x;
    int tid = threadIdx.x;
    const float4* row = reinterpret_cast<const float4*>(x + (size_t)t * D);
    float4 v = row[tid];
    float s = v.x + v.y + v.z + v.w;
    float ss = v.x * v.x + v.y * v.y + v.z * v.z + v.w * v.w;
#pragma unroll
    for (int o = 16; o > 0; o >>= 1) {
        s += __shfl_xor_sync(0xffffffffu, s, o);
        ss += __shfl_xor_sync(0xffffffffu, ss, o);
    }
    __shared__ float red_s[8], red_ss[8];
    int w = tid >> 5;
    if ((tid & 31) == 0) { red_s[w] = s; red_ss[w] = ss; }
    __syncthreads();
    s = 0.f; ss = 0.f;
#pragma unroll
    for (int i = 0; i < 8; i++) { s += red_s[i]; ss += red_ss[i]; }
    float mu = s * (1.f / (float)D);
    float var = ss * (1.f / (float)D) - mu * mu;
    float inv = rsqrtf(var + LN_EPS);
    float4 g = reinterpret_cast<const float4*>(gamma)[tid];
    float4 bb = reinterpret_cast<const float4*>(beta)[tid];
    float4 o;
    o.x = (v.x - mu) * inv * g.x + bb.x;
    o.y = (v.y - mu) * inv * g.y + bb.y;
    o.z = (v.z - mu) * inv * g.z + bb.z;
    o.w = (v.w - mu) * inv * g.w + bb.w;
    reinterpret_cast<float4*>(g_xn + (size_t)t * D)[tid] = o;
}

// ----------------------------------------------------------------------------
// tf32 / cp.async helpers
// ----------------------------------------------------------------------------
__device__ __forceinline__ float to_tf32(float x) {
    float r;
    asm("cvt.rna.tf32.f32 %0, %1;" : "=f"(r) : "f"(x));
    return r;
}

__device__ __forceinline__ void mma_tf32(float* d, const uint32_t* a, const uint32_t* b) {
    asm volatile(
        "mma.sync.aligned.m16n8k8.row.col.f32.tf32.tf32.f32 "
        "{%0,%1,%2,%3}, {%4,%5,%6,%7}, {%8,%9}, {%0,%1,%2,%3};"
        : "+f"(d[0]), "+f"(d[1]), "+f"(d[2]), "+f"(d[3])
        : "r"(a[0]), "r"(a[1]), "r"(a[2]), "r"(a[3]), "r"(b[0]), "r"(b[1]));
}

__device__ __forceinline__ void cp_async16(uint32_t smem_addr, const void* gptr) {
    asm volatile("cp.async.cg.shared.global [%0], [%1], 16;" ::
                 "r"(smem_addr), "l"(gptr));
}

// ----------------------------------------------------------------------------
// GEMM core (tensor pipe): C[4096,1024] = A[M,K] @ W[N,K]^T + bias (+res)
// cp.async 2-stage double buffer, BK=16, 256 threads, 8 warps (4m x 2n),
// warp tile 32x64, mma m16n8k8 tf32 (inputs truncated by HW, no cvt).
// ----------------------------------------------------------------------------
template <bool RES>
__device__ __forceinline__ void gemm_core_mma(const float* __restrict__ A,
                                              const float* __restrict__ W,
                                              const float* __restrict__ bias,
                                              const float* __restrict__ res,
                                              float* __restrict__ C) {
    __shared__ float As[2][BM * LDK];
    __shared__ float Bs[2][BN * LDK];
    const int tid = threadIdx.x;
    const int lane = tid & 31;
    const int wid = tid >> 5;
    const int wm = (wid & 3) * 32;
    const int wn = (wid >> 2) * 64;
    const int g = lane >> 2;
    const int tg = lane & 3;
    const int m0 = blockIdx.y * BM;
    const int n0 = blockIdx.x * BN;

    float c[2][8][4];
#pragma unroll
    for (int mt = 0; mt < 2; mt++)
#pragma unroll
        for (int nt = 0; nt < 8; nt++)
#pragma unroll
            for (int i = 0; i < 4; i++) c[mt][nt][i] = 0.f;

    // async loaders: 256 threads x 4 cp.async(16B) per stage
    const int lr = tid >> 2;        // 0..63
    const int lc = (tid & 3) * 4;   // k offset 0,4,8,12

    const float* gA0 = A + (size_t)(m0 + lr) * D + lc;
    const float* gA1 = A + (size_t)(m0 + lr + 64) * D + lc;
    const float* gB0 = W + (size_t)(n0 + lr) * D + lc;
    const float* gB1 = W + (size_t)(n0 + lr + 64) * D + lc;

    uint32_t sA0[2], sA1[2], sB0[2], sB1[2];
#pragma unroll
    for (int s = 0; s < 2; s++) {
        sA0[s] = (uint32_t)__cvta_generic_to_shared(&As[s][lr * LDK + lc]);
        sA1[s] = (uint32_t)__cvta_generic_to_shared(&As[s][(lr + 64) * LDK + lc]);
        sB0[s] = (uint32_t)__cvta_generic_to_shared(&Bs[s][lr * LDK + lc]);
        sB1[s] = (uint32_t)__cvta_generic_to_shared(&Bs[s][(lr + 64) * LDK + lc]);
    }

    // prologue: stage 0, k-slice 0
    cp_async16(sA0[0], gA0);
    cp_async16(sA1[0], gA1);
    cp_async16(sB0[0], gB0);
    cp_async16(sB1[0], gB1);
    asm volatile("cp.async.commit_group;");

    for (int k0 = 0; k0 < NK; k0++) {
        const int s = k0 & 1;
        __syncthreads();  // all warps done reading stage s^1 (prev-prev slice)
        if (k0 + 1 < NK) {
            const int koff = (k0 + 1) * BK;
            cp_async16(sA0[s ^ 1], gA0 + koff);
            cp_async16(sA1[s ^ 1], gA1 + koff);
            cp_async16(sB0[s ^ 1], gB0 + koff);
            cp_async16(sB1[s ^ 1], gB1 + koff);
            asm volatile("cp.async.commit_group;");
            asm volatile("cp.async.wait_group 1;");
        } else {
            asm volatile("cp.async.wait_group 0;");
        }
        __syncthreads();  // stage s data visible to all warps

        uint32_t af[2][2][4];
        const uint32_t* Asu = reinterpret_cast<const uint32_t*>(As[s]);
#pragma unroll
        for (int mt = 0; mt < 2; mt++) {
            int r0 = wm + mt * 16 + g;
#pragma unroll
            for (int kt = 0; kt < 2; kt++) {
                int cbase = kt * 8 + tg;
                af[mt][kt][0] = Asu[r0 * LDK + cbase];
                af[mt][kt][1] = Asu[(r0 + 8) * LDK + cbase];
                af[mt][kt][2] = Asu[r0 * LDK + cbase + 4];
                af[mt][kt][3] = Asu[(r0 + 8) * LDK + cbase + 4];
            }
        }
        const uint32_t* Bsu = reinterpret_cast<const uint32_t*>(Bs[s]);
#pragma unroll
        for (int nt = 0; nt < 8; nt++) {
            int nr = wn + nt * 8 + g;
            uint32_t bf[2][2];
#pragma unroll
            for (int kt = 0; kt < 2; kt++) {
                int cbase = kt * 8 + tg;
                bf[kt][0] = Bsu[nr * LDK + cbase];
                bf[kt][1] = Bsu[nr * LDK + cbase + 4];
            }
#pragma unroll
            for (int mt = 0; mt < 2; mt++) {
#pragma unroll
                for (int kt = 0; kt < 2; kt++) {
                    mma_tf32(c[mt][nt], af[mt][kt], bf[kt]);
                }
            }
        }
    }

    // epilogue: bias (+ residual), float2 stores
#pragma unroll
    for (int nt = 0; nt < 8; nt++) {
        int col = n0 + wn + nt * 8 + 2 * tg;
        float2 bi = *reinterpret_cast<const float2*>(bias + col);
#pragma unroll
        for (int mt = 0; mt < 2; mt++) {
            int r0 = m0 + wm + mt * 16 + g;
#pragma unroll
            for (int half = 0; half < 2; half++) {
                int r = r0 + half * 8;
                size_t off = (size_t)r * D + col;
                float2 o;
                o.x = c[mt][nt][half * 2 + 0] + bi.x;
                o.y = c[mt][nt][half * 2 + 1] + bi.y;
                if (RES) {
                    float2 rr = *reinterpret_cast<const float2*>(res + off);
                    o.x += rr.x; o.y += rr.y;
                }
                *reinterpret_cast<float2*>(C + off) = o;
            }
        }
    }
}

__global__ __launch_bounds__(256) void gemm_qkv_kernel(
    const float* __restrict__ wq, const float* __restrict__ wk,
    const float* __restrict__ wv, const float* __restrict__ bq,
    const float* __restrict__ bk, const float* __restrict__ bv) {
    const float* Wm;
    const float* bias;
    float* out;
    if (blockIdx.z == 0)      { Wm = wq; bias = bq; out = g_q; }
    else if (blockIdx.z == 1) { Wm = wk; bias = bk; out = g_k; }
    else                      { Wm = wv; bias = bv; out = g_v; }
    gemm_core_mma<false>(g_xn, Wm, bias, nullptr, out);
}

__global__ __launch_bounds__(256) void gemm_out_kernel(
    const float* __restrict__ wo, const float* __restrict__ bo,
    const float* __restrict__ residual, float* __restrict__ out) {
    gemm_core_mma<true>(g_ctx, wo, bo, residual, out);
}

// ----------------------------------------------------------------------------
// Flash attention, tf32 mma m16n8k8 (unchanged from R6 passing version).
// grid = (S/128=16, H=16, B=2), 256 threads.
// ----------------------------------------------------------------------------
__global__ __launch_bounds__(256, 1) void attn_mma_kernel(const float* __restrict__ mask) {
    __shared__ float buf[ABQ * LDA];   // Q stage, then K(0..64*LDA) / Vt(64*LDA..)
    __shared__ float Ms_[ABK];
    float* Ks = buf;
    float* Vt = buf + 64 * LDA;

    const int qt = blockIdx.x;
    const int h = blockIdx.y;
    const int b = blockIdx.z;
    const int tid = threadIdx.x;
    const int lane = tid & 31;
    const int wid = tid >> 5;
    const int g = lane >> 2;
    const int tg = lane & 3;
    const int wm = wid * 16;
    const size_t base = (size_t)b * S * D + (size_t)h * HD;

    // ---- stage Q (scaled, tf32) into buf, extract per-warp fragments ----
    {
        int r = tid >> 1;
        const float* qrow = g_q + base + (size_t)(qt * ABQ + r) * D;
#pragma unroll
        for (int j = 0; j < 8; j++) {
            int c4 = (tid & 1) * 8 + j;
            float4 v = *reinterpret_cast<const float4*>(qrow + c4 * 4);
            float* dst = buf + r * LDA + c4 * 4;
            dst[0] = to_tf32(v.x * SCALE);
            dst[1] = to_tf32(v.y * SCALE);
            dst[2] = to_tf32(v.z * SCALE);
            dst[3] = to_tf32(v.w * SCALE);
        }
    }
    __syncthreads();

    uint32_t aq[8][4];
    {
        const uint32_t* Qu = reinterpret_cast<const uint32_t*>(buf);
#pragma unroll
        for (int dk = 0; dk < 8; dk++) {
            int cb = dk * 8 + tg;
            aq[dk][0] = Qu[(wm + g) * LDA + cb];
            aq[dk][1] = Qu[(wm + g + 8) * LDA + cb];
            aq[dk][2] = Qu[(wm + g) * LDA + cb + 4];
            aq[dk][3] = Qu[(wm + g + 8) * LDA + cb + 4];
        }
    }
    __syncthreads();  // done with Q stage; buf becomes K/Vt

    float co[8][4];
#pragma unroll
    for (int nt = 0; nt < 8; nt++)
#pragma unroll
        for (int i = 0; i < 4; i++) co[nt][i] = 0.f;
    float m0 = -1e30f, m1 = -1e30f, l0 = 0.f, l1 = 0.f;

    const int key_of_t = tid >> 2;
    const int c4base = tid & 3;

    for (int kt0 = 0; kt0 < S; kt0 += ABK) {
        const float* krow = g_k + base + (size_t)(kt0 + key_of_t) * D;
        const float* vrow = g_v + base + (size_t)(kt0 + key_of_t) * D;
#pragma unroll
        for (int j = 0; j < 4; j++) {
            int c4 = c4base + j * 4;
            float4 kv = *reinterpret_cast<const float4*>(krow + c4 * 4);
            float* kd = Ks + key_of_t * LDA + c4 * 4;
            kd[0] = to_tf32(kv.x); kd[1] = to_tf32(kv.y);
            kd[2] = to_tf32(kv.z); kd[3] = to_tf32(kv.w);
            float4 vv = *reinterpret_cast<const float4*>(vrow + c4 * 4);
            Vt[(c4 * 4 + 0) * LDA + key_of_t] = to_tf32(vv.x);
            Vt[(c4 * 4 + 1) * LDA + key_of_t] = to_tf32(vv.y);
            Vt[(c4 * 4 + 2) * LDA + key_of_t] = to_tf32(vv.z);
            Vt[(c4 * 4 + 3) * LDA + key_of_t] = to_tf32(vv.w);
        }
        if (tid < ABK) Ms_[tid] = mask[(size_t)b * S + kt0 + tid];
        __syncthreads();

        float cs[8][4];
#pragma unroll
        for (int nt = 0; nt < 8; nt++)
#pragma unroll
            for (int i = 0; i < 4; i++) cs[nt][i] = 0.f;

        const uint32_t* Ksu = reinterpret_cast<const uint32_t*>(Ks);
#pragma unroll
        for (int dk = 0; dk < 8; dk++) {
#pragma unroll
            for (int nt = 0; nt < 8; nt++) {
                uint32_t bf[2];
                bf[0] = Ksu[(nt * 8 + g) * LDA + dk * 8 + tg];
                bf[1] = Ksu[(nt * 8 + g) * LDA + dk * 8 + tg + 4];
                mma_tf32(cs[nt], aq[dk], bf);
            }
        }

        float mx0 = -1e30f, mx1 = -1e30f;
#pragma unroll
        for (int nt = 0; nt < 8; nt++) {
            float mk0 = Ms_[nt * 8 + 2 * tg];
            float mk1 = Ms_[nt * 8 + 2 * tg + 1];
            cs[nt][0] += mk0; cs[nt][1] += mk1;
            cs[nt][2] += mk0; cs[nt][3] += mk1;
            mx0 = fmaxf(mx0, fmaxf(cs[nt][0], cs[nt][1]));
            mx1 = fmaxf(mx1, fmaxf(cs[nt][2], cs[nt][3]));
        }
        mx0 = fmaxf(mx0, __shfl_xor_sync(0xffffffffu, mx0, 1));
        mx0 = fmaxf(mx0, __shfl_xor_sync(0xffffffffu, mx0, 2));
        mx1 = fmaxf(mx1, __shfl_xor_sync(0xffffffffu, mx1, 1));
        mx1 = fmaxf(mx1, __shfl_xor_sync(0xffffffffu, mx1, 2));

        float mn0 = fmaxf(m0, mx0);
        float mn1 = fmaxf(m1, mx1);
        float cr0 = __expf(m0 - mn0);
        float cr1 = __expf(m1 - mn1);
        m0 = mn0; m1 = mn1;
        l0 *= cr0; l1 *= cr1;

        uint32_t pu[8][4];
#pragma unroll
        for (int nt = 0; nt < 8; nt++) {
            float p0 = __expf(cs[nt][0] - m0);
            float p1 = __expf(cs[nt][1] - m0);
            float p2 = __expf(cs[nt][2] - m1);
            float p3 = __expf(cs[nt][3] - m1);
            l0 += p0 + p1;
            l1 += p2 + p3;
            pu[nt][0] = __float_as_uint(to_tf32(p0));
            pu[nt][1] = __float_as_uint(to_tf32(p1));
            pu[nt][2] = __float_as_uint(to_tf32(p2));
            pu[nt][3] = __float_as_uint(to_tf32(p3));
            co[nt][0] *= cr0; co[nt][1] *= cr0;
            co[nt][2] *= cr1; co[nt][3] *= cr1;
        }

        const uint32_t* Vtu = reinterpret_cast<const uint32_t*>(Vt);
        const int srcA = (lane & ~3) | (tg >> 1);
        const int srcB = srcA + 2;
#pragma unroll
        for (int kk = 0; kk < 8; kk++) {
            uint32_t v00 = __shfl_sync(0xffffffffu, pu[kk][0], srcA);
            uint32_t v01 = __shfl_sync(0xffffffffu, pu[kk][1], srcA);
            uint32_t v10 = __shfl_sync(0xffffffffu, pu[kk][2], srcA);
            uint32_t v11 = __shfl_sync(0xffffffffu, pu[kk][3], srcA);
            uint32_t w00 = __shfl_sync(0xffffffffu, pu[kk][0], srcB);
            uint32_t w01 = __shfl_sync(0xffffffffu, pu[kk][1], srcB);
            uint32_t w10 = __shfl_sync(0xffffffffu, pu[kk][2], srcB);
            uint32_t w11 = __shfl_sync(0xffffffffu, pu[kk][3], srcB);
            uint32_t ap[4];
            ap[0] = (tg & 1) ? v01 : v00;
            ap[1] = (tg & 1) ? v11 : v10;
            ap[2] = (tg & 1) ? w01 : w00;
            ap[3] = (tg & 1) ? w11 : w10;
#pragma unroll
            for (int nt = 0; nt < 8; nt++) {
                uint32_t bf[2];
                bf[0] = Vtu[(nt * 8 + g) * LDA + kk * 8 + tg];
                bf[1] = Vtu[(nt * 8 + g) * LDA + kk * 8 + tg + 4];
                mma_tf32(co[nt], ap, bf);
            }
        }
        __syncthreads();
    }

    l0 += __shfl_xor_sync(0xffffffffu, l0, 1);
    l0 += __shfl_xor_sync(0xffffffffu, l0, 2);
    l1 += __shfl_xor_sync(0xffffffffu, l1, 1);
    l1 += __shfl_xor_sync(0xffffffffu, l1, 2);
    float inv0 = 1.f / l0;
    float inv1 = 1.f / l1;

    const int qr0 = qt * ABQ + wm + g;
#pragma unroll
    for (int nt = 0; nt < 8; nt++) {
        int col = nt * 8 + 2 * tg;
        float2 o0, o1;
        o0.x = co[nt][0] * inv0; o0.y = co[nt][1] * inv0;
        o1.x = co[nt][2] * inv1; o1.y = co[nt][3] * inv1;
        *reinterpret_cast<float2*>(g_ctx + base + (size_t)qr0 * D + col) = o0;
        *reinterpret_cast<float2*>(g_ctx + base + (size_t)(qr0 + 8) * D + col) = o1;
    }
}

// ----------------------------------------------------------------------------
// Launch
// ----------------------------------------------------------------------------
extern "C" void kernel_launch(void* const* d_in, const int* in_sizes, int n_in,
                              void* d_out, int out_size) {
    (void)in_sizes; (void)n_in; (void)out_size;
    const float* hidden = (const float*)d_in[0];
    const float* mask   = (const float*)d_in[1];
    const float* gamma  = (const float*)d_in[2];
    const float* beta   = (const float*)d_in[3];
    const float* wq = (const float*)d_in[4];
    const float* bq = (const float*)d_in[5];
    const float* wk = (const float*)d_in[6];
    const float* bk = (const float*)d_in[7];
    const float* wv = (const float*)d_in[8];
    const float* bv = (const float*)d_in[9];
    const float* wo = (const float*)d_in[10];
    const float* bo = (const float*)d_in[11];
    float* out = (float*)d_out;

    ln_kernel<<<T, 256>>>(hidden, gamma, beta);

    dim3 gqkv(D / BN, T / BM, 3);  // (8, 32, 3)
    gemm_qkv_kernel<<<gqkv, 256>>>(wq, wk, wv, bq, bk, bv);

    dim3 gattn(S / ABQ, H, B);  // (16, 16, 2)
    attn_mma_kernel<<<gattn, 256>>>(mask);

    dim3 gout(D / BN, T / BM);  // (8, 32)
    gemm_out_kernel<<<gout, 256>>>(wo, bo, hidden, out);
}

// round 12
// speedup vs baseline: 3.7344x; 1.0086x over previous
#include <cuda_runtime.h>
#include <cstdint>

// ============================================================================
// GroupBertAttention: pre-LN -> QKV proj -> MHA (softmax) -> out proj + residual
// B=2, S=2048, D=1024, H=16, hd=64, fp32 in/out.
// Round 12: linear GEMMs -> 3-stage cp.async pipeline, ONE __syncthreads per
// k-iteration (barrier-bound fix; R11 ncu: tensor 33%, issue 20%, 2 BARs/iter).
// Attention unchanged from the R6/R11 passing MMA-flash kernel.
// ============================================================================

namespace {
constexpr int B = 2, S = 2048, D = 1024, H = 16, HD = 64;
constexpr int T = B * S;  // 4096 tokens
constexpr float LN_EPS = 1e-12f;
constexpr float SCALE = 0.125f;  // 1/sqrt(64)

// mma GEMM tiling
constexpr int BM = 128, BN = 128, BK = 16;
constexpr int LDK = 20;              // padded smem row stride (conflict-free frags)
constexpr int NK = D / BK;           // 64
constexpr int NSTAGE = 3;
constexpr int STAGE_F = (BM + BN) * LDK;              // floats per stage
constexpr int SMEM_GEMM = NSTAGE * STAGE_F * 4;       // 61440 bytes

// attention tiling
constexpr int ABQ = 128;   // queries per block
constexpr int ABK = 64;    // keys per tile
constexpr int LDA = 68;    // padded smem row stride for 64-wide tiles
}  // namespace

// Scratch (device globals; no allocation allowed in kernel_launch)
__device__ float g_xn[T * D];
__device__ float g_q[T * D];
__device__ float g_k[T * D];
__device__ float g_v[T * D];
__device__ float g_ctx[T * D];

// ----------------------------------------------------------------------------
// LayerNorm: one block per token, 256 threads x 4 elems
// ----------------------------------------------------------------------------
__global__ __launch_bounds__(256) void ln_kernel(const float* __restrict__ x,
                                                 const float* __restrict__ gamma,
                                                 const float* __restrict__ beta) {
    int t = blockIdx.x;
    int tid = threadIdx.x;
    const float4* row = reinterpret_cast<const float4*>(x + (size_t)t * D);
    float4 v = row[tid];
    float s = v.x + v.y + v.z + v.w;
    float ss = v.x * v.x + v.y * v.y + v.z * v.z + v.w * v.w;
#pragma unroll
    for (int o = 16; o > 0; o >>= 1) {
        s += __shfl_xor_sync(0xffffffffu, s, o);
        ss += __shfl_xor_sync(0xffffffffu, ss, o);
    }
    __shared__ float red_s[8], red_ss[8];
    int w = tid >> 5;
    if ((tid & 31) == 0) { red_s[w] = s; red_ss[w] = ss; }
    __syncthreads();
    s = 0.f; ss = 0.f;
#pragma unroll
    for (int i = 0; i < 8; i++) { s += red_s[i]; ss += red_ss[i]; }
    float mu = s * (1.f / (float)D);
    float var = ss * (1.f / (float)D) - mu * mu;
    float inv = rsqrtf(var + LN_EPS);
    float4 g = reinterpret_cast<const float4*>(gamma)[tid];
    float4 bb = reinterpret_cast<const float4*>(beta)[tid];
    float4 o;
    o.x = (v.x - mu) * inv * g.x + bb.x;
    o.y = (v.y - mu) * inv * g.y + bb.y;
    o.z = (v.z - mu) * inv * g.z + bb.z;
    o.w = (v.w - mu) * inv * g.w + bb.w;
    reinterpret_cast<float4*>(g_xn + (size_t)t * D)[tid] = o;
}

// ----------------------------------------------------------------------------
// tf32 / cp.async helpers
// ----------------------------------------------------------------------------
__device__ __forceinline__ float to_tf32(float x) {
    float r;
    asm("cvt.rna.tf32.f32 %0, %1;" : "=f"(r) : "f"(x));
    return r;
}

__device__ __forceinline__ void mma_tf32(float* d, const uint32_t* a, const uint32_t* b) {
    asm volatile(
        "mma.sync.aligned.m16n8k8.row.col.f32.tf32.tf32.f32 "
        "{%0,%1,%2,%3}, {%4,%5,%6,%7}, {%8,%9}, {%0,%1,%2,%3};"
        : "+f"(d[0]), "+f"(d[1]), "+f"(d[2]), "+f"(d[3])
        : "r"(a[0]), "r"(a[1]), "r"(a[2]), "r"(a[3]), "r"(b[0]), "r"(b[1]));
}

__device__ __forceinline__ void cp_async16(uint32_t smem_addr, const void* gptr) {
    asm volatile("cp.async.cg.shared.global [%0], [%1], 16;" ::
                 "r"(smem_addr), "l"(gptr));
}

// ----------------------------------------------------------------------------
// GEMM core (tensor pipe): C[4096,1024] = A[M,K] @ W[N,K]^T + bias (+res)
// 3-stage cp.async pipeline, ONE sync per iter, BK=16, 256 threads,
// 8 warps (4m x 2n), warp tile 32x64, mma m16n8k8 tf32 (HW truncation).
// Stage s of dynamic smem: A at s*STAGE_F, B at s*STAGE_F + BM*LDK.
// Hazard proof for single sync: write target at iter k is stage (k+2)%3 ==
// (k-1)%3, whose only readers ran in compute(k-1); sync(k) orders them before
// the writes. wait_group 1 at iter k (2 groups committed) => slice k arrived.
// ----------------------------------------------------------------------------
template <bool RES>
__device__ __forceinline__ void gemm_core_mma(const float* __restrict__ A,
                                              const float* __restrict__ W,
                                              const float* __restrict__ bias,
                                              const float* __restrict__ res,
                                              float* __restrict__ C) {
    extern __shared__ float smem[];
    const int tid = threadIdx.x;
    const int lane = tid & 31;
    const int wid = tid >> 5;
    const int wm = (wid & 3) * 32;
    const int wn = (wid >> 2) * 64;
    const int g = lane >> 2;
    const int tg = lane & 3;
    const int m0 = blockIdx.y * BM;
    const int n0 = blockIdx.x * BN;

    float c[2][8][4];
#pragma unroll
    for (int mt = 0; mt < 2; mt++)
#pragma unroll
        for (int nt = 0; nt < 8; nt++)
#pragma unroll
            for (int i = 0; i < 4; i++) c[mt][nt][i] = 0.f;

    // async loaders: 256 threads x 4 cp.async(16B) per stage
    const int lr = tid >> 2;        // 0..63
    const int lc = (tid & 3) * 4;   // k offset 0,4,8,12

    const float* gA0 = A + (size_t)(m0 + lr) * D + lc;
    const float* gA1 = A + (size_t)(m0 + lr + 64) * D + lc;
    const float* gB0 = W + (size_t)(n0 + lr) * D + lc;
    const float* gB1 = W + (size_t)(n0 + lr + 64) * D + lc;

    uint32_t sA0[NSTAGE], sA1[NSTAGE], sB0[NSTAGE], sB1[NSTAGE];
#pragma unroll
    for (int s = 0; s < NSTAGE; s++) {
        float* As_ = smem + s * STAGE_F;
        float* Bs_ = As_ + BM * LDK;
        sA0[s] = (uint32_t)__cvta_generic_to_shared(As_ + lr * LDK + lc);
        sA1[s] = (uint32_t)__cvta_generic_to_shared(As_ + (lr + 64) * LDK + lc);
        sB0[s] = (uint32_t)__cvta_generic_to_shared(Bs_ + lr * LDK + lc);
        sB1[s] = (uint32_t)__cvta_generic_to_shared(Bs_ + (lr + 64) * LDK + lc);
    }

    // prologue: slices 0 and 1 into stages 0 and 1 (two commit groups)
#pragma unroll
    for (int p = 0; p < 2; p++) {
        const int koff = p * BK;
        cp_async16(sA0[p], gA0 + koff);
        cp_async16(sA1[p], gA1 + koff);
        cp_async16(sB0[p], gB0 + koff);
        cp_async16(sB1[p], gB1 + koff);
        asm volatile("cp.async.commit_group;");
    }

    int s = 0;        // compute stage for iter k0
    int sw = 2;       // write stage for slice k0+2
    for (int k0 = 0; k0 < NK; k0++) {
        if (k0 + 1 < NK) {
            asm volatile("cp.async.wait_group 1;");
        } else {
            asm volatile("cp.async.wait_group 0;");
        }
        __syncthreads();  // the ONLY barrier per iteration

        if (k0 + 2 < NK) {
            const int koff = (k0 + 2) * BK;
            cp_async16(sA0[sw], gA0 + koff);
            cp_async16(sA1[sw], gA1 + koff);
            cp_async16(sB0[sw], gB0 + koff);
            cp_async16(sB1[sw], gB1 + koff);
            asm volatile("cp.async.commit_group;");
        }

        uint32_t af[2][2][4];
        const uint32_t* Asu = reinterpret_cast<const uint32_t*>(smem + s * STAGE_F);
#pragma unroll
        for (int mt = 0; mt < 2; mt++) {
            int r0 = wm + mt * 16 + g;
#pragma unroll
            for (int kt = 0; kt < 2; kt++) {
                int cbase = kt * 8 + tg;
                af[mt][kt][0] = Asu[r0 * LDK + cbase];
                af[mt][kt][1] = Asu[(r0 + 8) * LDK + cbase];
                af[mt][kt][2] = Asu[r0 * LDK + cbase + 4];
                af[mt][kt][3] = Asu[(r0 + 8) * LDK + cbase + 4];
            }
        }
        const uint32_t* Bsu = Asu + BM * LDK;
#pragma unroll
        for (int nt = 0; nt < 8; nt++) {
            int nr = wn + nt * 8 + g;
            uint32_t bf[2][2];
#pragma unroll
            for (int kt = 0; kt < 2; kt++) {
                int cbase = kt * 8 + tg;
                bf[kt][0] = Bsu[nr * LDK + cbase];
                bf[kt][1] = Bsu[nr * LDK + cbase + 4];
            }
#pragma unroll
            for (int mt = 0; mt < 2; mt++) {
#pragma unroll
                for (int kt = 0; kt < 2; kt++) {
                    mma_tf32(c[mt][nt], af[mt][kt], bf[kt]);
                }
            }
        }

        s = (s == NSTAGE - 1) ? 0 : s + 1;
        sw = (sw == NSTAGE - 1) ? 0 : sw + 1;
    }

    // epilogue: bias (+ residual), float2 stores
#pragma unroll
    for (int nt = 0; nt < 8; nt++) {
        int col = n0 + wn + nt * 8 + 2 * tg;
        float2 bi = *reinterpret_cast<const float2*>(bias + col);
#pragma unroll
        for (int mt = 0; mt < 2; mt++) {
            int r0 = m0 + wm + mt * 16 + g;
#pragma unroll
            for (int half = 0; half < 2; half++) {
                int r = r0 + half * 8;
                size_t off = (size_t)r * D + col;
                float2 o;
                o.x = c[mt][nt][half * 2 + 0] + bi.x;
                o.y = c[mt][nt][half * 2 + 1] + bi.y;
                if (RES) {
                    float2 rr = *reinterpret_cast<const float2*>(res + off);
                    o.x += rr.x; o.y += rr.y;
                }
                *reinterpret_cast<float2*>(C + off) = o;
            }
        }
    }
}

__global__ __launch_bounds__(256) void gemm_qkv_kernel(
    const float* __restrict__ wq, const float* __restrict__ wk,
    const float* __restrict__ wv, const float* __restrict__ bq,
    const float* __restrict__ bk, const float* __restrict__ bv) {
    const float* Wm;
    const float* bias;
    float* out;
    if (blockIdx.z == 0)      { Wm = wq; bias = bq; out = g_q; }
    else if (blockIdx.z == 1) { Wm = wk; bias = bk; out = g_k; }
    else                      { Wm = wv; bias = bv; out = g_v; }
    gemm_core_mma<false>(g_xn, Wm, bias, nullptr, out);
}

__global__ __launch_bounds__(256) void gemm_out_kernel(
    const float* __restrict__ wo, const float* __restrict__ bo,
    const float* __restrict__ residual, float* __restrict__ out) {
    gemm_core_mma<true>(g_ctx, wo, bo, residual, out);
}

// ----------------------------------------------------------------------------
// Flash attention, tf32 mma m16n8k8 (unchanged from R6/R11 passing version).
// grid = (S/128=16, H=16, B=2), 256 threads.
// ----------------------------------------------------------------------------
__global__ __launch_bounds__(256, 1) void attn_mma_kernel(const float* __restrict__ mask) {
    __shared__ float buf[ABQ * LDA];   // Q stage, then K(0..64*LDA) / Vt(64*LDA..)
    __shared__ float Ms_[ABK];
    float* Ks = buf;
    float* Vt = buf + 64 * LDA;

    const int qt = blockIdx.x;
    const int h = blockIdx.y;
    const int b = blockIdx.z;
    const int tid = threadIdx.x;
    const int lane = tid & 31;
    const int wid = tid >> 5;
    const int g = lane >> 2;
    const int tg = lane & 3;
    const int wm = wid * 16;
    const size_t base = (size_t)b * S * D + (size_t)h * HD;

    // ---- stage Q (scaled, tf32) into buf, extract per-warp fragments ----
    {
        int r = tid >> 1;
        const float* qrow = g_q + base + (size_t)(qt * ABQ + r) * D;
#pragma unroll
        for (int j = 0; j < 8; j++) {
            int c4 = (tid & 1) * 8 + j;
            float4 v = *reinterpret_cast<const float4*>(qrow + c4 * 4);
            float* dst = buf + r * LDA + c4 * 4;
            dst[0] = to_tf32(v.x * SCALE);
            dst[1] = to_tf32(v.y * SCALE);
            dst[2] = to_tf32(v.z * SCALE);
            dst[3] = to_tf32(v.w * SCALE);
        }
    }
    __syncthreads();

    uint32_t aq[8][4];
    {
        const uint32_t* Qu = reinterpret_cast<const uint32_t*>(buf);
#pragma unroll
        for (int dk = 0; dk < 8; dk++) {
            int cb = dk * 8 + tg;
            aq[dk][0] = Qu[(wm + g) * LDA + cb];
            aq[dk][1] = Qu[(wm + g + 8) * LDA + cb];
            aq[dk][2] = Qu[(wm + g) * LDA + cb + 4];
            aq[dk][3] = Qu[(wm + g + 8) * LDA + cb + 4];
        }
    }
    __syncthreads();  // done with Q stage; buf becomes K/Vt

    float co[8][4];
#pragma unroll
    for (int nt = 0; nt < 8; nt++)
#pragma unroll
        for (int i = 0; i < 4; i++) co[nt][i] = 0.f;
    float m0 = -1e30f, m1 = -1e30f, l0 = 0.f, l1 = 0.f;

    const int key_of_t = tid >> 2;
    const int c4base = tid & 3;

    for (int kt0 = 0; kt0 < S; kt0 += ABK) {
        const float* krow = g_k + base + (size_t)(kt0 + key_of_t) * D;
        const float* vrow = g_v + base + (size_t)(kt0 + key_of_t) * D;
#pragma unroll
        for (int j = 0; j < 4; j++) {
            int c4 = c4base + j * 4;
            float4 kv = *reinterpret_cast<const float4*>(krow + c4 * 4);
            float* kd = Ks + key_of_t * LDA + c4 * 4;
            kd[0] = to_tf32(kv.x); kd[1] = to_tf32(kv.y);
            kd[2] = to_tf32(kv.z); kd[3] = to_tf32(kv.w);
            float4 vv = *reinterpret_cast<const float4*>(vrow + c4 * 4);
            Vt[(c4 * 4 + 0) * LDA + key_of_t] = to_tf32(vv.x);
            Vt[(c4 * 4 + 1) * LDA + key_of_t] = to_tf32(vv.y);
            Vt[(c4 * 4 + 2) * LDA + key_of_t] = to_tf32(vv.z);
            Vt[(c4 * 4 + 3) * LDA + key_of_t] = to_tf32(vv.w);
        }
        if (tid < ABK) Ms_[tid] = mask[(size_t)b * S + kt0 + tid];
        __syncthreads();

        float cs[8][4];
#pragma unroll
        for (int nt = 0; nt < 8; nt++)
#pragma unroll
            for (int i = 0; i < 4; i++) cs[nt][i] = 0.f;

        const uint32_t* Ksu = reinterpret_cast<const uint32_t*>(Ks);
#pragma unroll
        for (int dk = 0; dk < 8; dk++) {
#pragma unroll
            for (int nt = 0; nt < 8; nt++) {
                uint32_t bf[2];
                bf[0] = Ksu[(nt * 8 + g) * LDA + dk * 8 + tg];
                bf[1] = Ksu[(nt * 8 + g) * LDA + dk * 8 + tg + 4];
                mma_tf32(cs[nt], aq[dk], bf);
            }
        }

        float mx0 = -1e30f, mx1 = -1e30f;
#pragma unroll
        for (int nt = 0; nt < 8; nt++) {
            float mk0 = Ms_[nt * 8 + 2 * tg];
            float mk1 = Ms_[nt * 8 + 2 * tg + 1];
            cs[nt][0] += mk0; cs[nt][1] += mk1;
            cs[nt][2] += mk0; cs[nt][3] += mk1;
            mx0 = fmaxf(mx0, fmaxf(cs[nt][0], cs[nt][1]));
            mx1 = fmaxf(mx1, fmaxf(cs[nt][2], cs[nt][3]));
        }
        mx0 = fmaxf(mx0, __shfl_xor_sync(0xffffffffu, mx0, 1));
        mx0 = fmaxf(mx0, __shfl_xor_sync(0xffffffffu, mx0, 2));
        mx1 = fmaxf(mx1, __shfl_xor_sync(0xffffffffu, mx1, 1));
        mx1 = fmaxf(mx1, __shfl_xor_sync(0xffffffffu, mx1, 2));

        float mn0 = fmaxf(m0, mx0);
        float mn1 = fmaxf(m1, mx1);
        float cr0 = __expf(m0 - mn0);
        float cr1 = __expf(m1 - mn1);
        m0 = mn0; m1 = mn1;
        l0 *= cr0; l1 *= cr1;

        uint32_t pu[8][4];
#pragma unroll
        for (int nt = 0; nt < 8; nt++) {
            float p0 = __expf(cs[nt][0] - m0);
            float p1 = __expf(cs[nt][1] - m0);
            float p2 = __expf(cs[nt][2] - m1);
            float p3 = __expf(cs[nt][3] - m1);
            l0 += p0 + p1;
            l1 += p2 + p3;
            pu[nt][0] = __float_as_uint(to_tf32(p0));
            pu[nt][1] = __float_as_uint(to_tf32(p1));
            pu[nt][2] = __float_as_uint(to_tf32(p2));
            pu[nt][3] = __float_as_uint(to_tf32(p3));
            co[nt][0] *= cr0; co[nt][1] *= cr0;
            co[nt][2] *= cr1; co[nt][3] *= cr1;
        }

        const uint32_t* Vtu = reinterpret_cast<const uint32_t*>(Vt);
        const int srcA = (lane & ~3) | (tg >> 1);
        const int srcB = srcA + 2;
#pragma unroll
        for (int kk = 0; kk < 8; kk++) {
            uint32_t v00 = __shfl_sync(0xffffffffu, pu[kk][0], srcA);
            uint32_t v01 = __shfl_sync(0xffffffffu, pu[kk][1], srcA);
            uint32_t v10 = __shfl_sync(0xffffffffu, pu[kk][2], srcA);
            uint32_t v11 = __shfl_sync(0xffffffffu, pu[kk][3], srcA);
            uint32_t w00 = __shfl_sync(0xffffffffu, pu[kk][0], srcB);
            uint32_t w01 = __shfl_sync(0xffffffffu, pu[kk][1], srcB);
            uint32_t w10 = __shfl_sync(0xffffffffu, pu[kk][2], srcB);
            uint32_t w11 = __shfl_sync(0xffffffffu, pu[kk][3], srcB);
            uint32_t ap[4];
            ap[0] = (tg & 1) ? v01 : v00;
            ap[1] = (tg & 1) ? v11 : v10;
            ap[2] = (tg & 1) ? w01 : w00;
            ap[3] = (tg & 1) ? w11 : w10;
#pragma unroll
            for (int nt = 0; nt < 8; nt++) {
                uint32_t bf[2];
                bf[0] = Vtu[(nt * 8 + g) * LDA + kk * 8 + tg];
                bf[1] = Vtu[(nt * 8 + g) * LDA + kk * 8 + tg + 4];
                mma_tf32(co[nt], ap, bf);
            }
        }
        __syncthreads();
    }

    l0 += __shfl_xor_sync(0xffffffffu, l0, 1);
    l0 += __shfl_xor_sync(0xffffffffu, l0, 2);
    l1 += __shfl_xor_sync(0xffffffffu, l1, 1);
    l1 += __shfl_xor_sync(0xffffffffu, l1, 2);
    float inv0 = 1.f / l0;
    float inv1 = 1.f / l1;

    const int qr0 = qt * ABQ + wm + g;
#pragma unroll
    for (int nt = 0; nt < 8; nt++) {
        int col = nt * 8 + 2 * tg;
        float2 o0, o1;
        o0.x = co[nt][0] * inv0; o0.y = co[nt][1] * inv0;
        o1.x = co[nt][2] * inv1; o1.y = co[nt][3] * inv1;
        *reinterpret_cast<float2*>(g_ctx + base + (size_t)qr0 * D + col) = o0;
        *reinterpret_cast<float2*>(g_ctx + base + (size_t)(qr0 + 8) * D + col) = o1;
    }
}

// ----------------------------------------------------------------------------
// Launch
// ----------------------------------------------------------------------------
extern "C" void kernel_launch(void* const* d_in, const int* in_sizes, int n_in,
                              void* d_out, int out_size) {
    (void)in_sizes; (void)n_in; (void)out_size;
    const float* hidden = (const float*)d_in[0];
    const float* mask   = (const float*)d_in[1];
    const float* gamma  = (const float*)d_in[2];
    const float* beta   = (const float*)d_in[3];
    const float* wq = (const float*)d_in[4];
    const float* bq = (const float*)d_in[5];
    const float* wk = (const float*)d_in[6];
    const float* bk = (const float*)d_in[7];
    const float* wv = (const float*)d_in[8];
    const float* bv = (const float*)d_in[9];
    const float* wo = (const float*)d_in[10];
    const float* bo = (const float*)d_in[11];
    float* out = (float*)d_out;

    // dynamic smem opt-in (61,440 B > 48 KB default). Host-side attribute set,
    // idempotent, no allocation — graph-capture safe.
    cudaFuncSetAttribute(gemm_qkv_kernel,
                         cudaFuncAttributeMaxDynamicSharedMemorySize, SMEM_GEMM);
    cudaFuncSetAttribute(gemm_out_kernel,
                         cudaFuncAttributeMaxDynamicSharedMemorySize, SMEM_GEMM);

    ln_kernel<<<T, 256>>>(hidden, gamma, beta);

    dim3 gqkv(D / BN, T / BM, 3);  // (8, 32, 3)
    gemm_qkv_kernel<<<gqkv, 256, SMEM_GEMM>>>(wq, wk, wv, bq, bk, bv);

    dim3 gattn(S / ABQ, H, B);  // (16, 16, 2)
    attn_mma_kernel<<<gattn, 256>>>(mask);

    dim3 gout(D / BN, T / BM);  // (8, 32)
    gemm_out_kernel<<<gout, 256, SMEM_GEMM>>>(wo, bo, hidden, out);
}